// round 10
// baseline (speedup 1.0000x reference)
#include <cuda_runtime.h>
#include <math.h>

#define V_NODES 2048
#define D_F     128
#define NJ      8
#define NCHUNK  128                  // CTAs; 16 rows each
#define VC      16                   // nodes per chunk
#define NP      73                   // 1 + J + J^2 output planes
#define NPU     45                   // 1 + J + J*(J+1)/2 unique planes
#define THREADS 512

__device__ float        g_acc[NPU * D_F];  // zero at module load; finalizer resets
__device__ unsigned int g_cnt;             // ticket counter; finalizer resets

__global__ void __launch_bounds__(THREADS) k_fused(const float* __restrict__ W,
                                                   const float* __restrict__ f,
                                                   float* __restrict__ out) {
    __shared__ float sl[NJ][VC];             // lam[j][v-in-chunk]
    __shared__ float cbuf[2][NPU][D_F];      // combine buffer (45 KB)
    __shared__ int   sflag;

    const int tid  = threadIdx.x;
    const int warp = tid >> 5;               // 0..15 -> one W row each
    const int lane = tid & 31;
    const int c    = blockIdx.x;

    // ---------------- phase 1: deg + filter responses for 16 rows ----------
    {
        const int row = c * VC + warp;
        const float4* Wr = reinterpret_cast<const float4*>(W + (size_t)row * V_NODES);
        float4 x[8], y[8];
        #pragma unroll
        for (int i = 0; i < 8; i++) x[i] = __ldcs(&Wr[lane + 32 * i]);
        #pragma unroll
        for (int i = 0; i < 8; i++) y[i] = __ldcs(&Wr[lane + 32 * (i + 8)]);
        float s = 0.f;
        #pragma unroll
        for (int i = 0; i < 8; i++) s += ((x[i].x + x[i].y) + (x[i].z + x[i].w));
        #pragma unroll
        for (int i = 0; i < 8; i++) s += ((y[i].x + y[i].y) + (y[i].z + y[i].w));
        #pragma unroll
        for (int off = 16; off; off >>= 1) s += __shfl_down_sync(0xffffffffu, s, off);

        if (lane == 0) {
            float deg  = s;
            float dh2  = 1.0f / fmaxf(1.0f, deg);      // diag(D) * dhalf^2
            float E    = fabsf(deg * dh2);
            float logE = logf(E);
            const float A   = 3.0f * 0.69314718055994531f / 6.0f;  // R*ln(2)/(J-R+1)
            const float PI2 = 6.28318530717958648f;
            float ssum = 1.125f;                        // (R/2)*sum(d^2)+(R/2)*d0^2
            #pragma unroll
            for (int j = 2; j <= NJ; j++) {
                float xx  = logE - A * (float)(j - 1) / 3.0f;
                float wav = 0.0f;
                if (xx > -A && xx <= 0.0f)
                    wav = 0.5f - 0.5f * cosf(PI2 * xx / A);  // d=(.5,.5),K=1
                ssum -= wav * wav;
                sl[j - 1][warp] = wav;
            }
            sl[0][warp] = sqrtf(fmaxf(ssum, 0.0f));     // scaling function
        }
    }
    __syncthreads();

    // ---------------- phase 2: 45 unique partial planes --------------------
    const int d = tid & 127;                 // feature index
    const int g = tid >> 7;                  // v-group 0..3 (4 nodes each)

    float a0 = 0.f, a1[NJ], a2[36];
    #pragma unroll
    for (int i = 0; i < NJ; i++) a1[i] = 0.f;
    #pragma unroll
    for (int i = 0; i < 36; i++) a2[i] = 0.f;

    #pragma unroll
    for (int vv = 0; vv < 4; vv++) {
        const int v = g * 4 + vv;
        float fv = f[(size_t)(c * VC + v) * D_F + d];
        float af = fabsf(fv);
        a0 += fv;
        float w[NJ], p[NJ];
        #pragma unroll
        for (int j = 0; j < NJ; j++) {
            w[j] = sl[j][v];
            p[j] = w[j] * af;
            a1[j] += p[j];
        }
        int idx = 0;
        #pragma unroll
        for (int j1 = 0; j1 < NJ; j1++)
            #pragma unroll
            for (int j2 = j1; j2 < NJ; j2++) {
                a2[idx] += w[j2] * p[j1];
                idx++;
            }
    }

    // combine stage 1: groups 2,3 dump to smem
    if (g >= 2) {
        float* cb = &cbuf[g - 2][0][0];
        cb[d] = a0;
        #pragma unroll
        for (int j = 0; j < NJ; j++) cb[(1 + j) * D_F + d] = a1[j];
        #pragma unroll
        for (int i = 0; i < 36; i++) cb[(1 + NJ + i) * D_F + d] = a2[i];
    }
    __syncthreads();
    if (g < 2) {                              // groups 0,1 absorb 2,3
        const float* cb = &cbuf[g][0][0];
        a0 += cb[d];
        #pragma unroll
        for (int j = 0; j < NJ; j++) a1[j] += cb[(1 + j) * D_F + d];
        #pragma unroll
        for (int i = 0; i < 36; i++) a2[i] += cb[(1 + NJ + i) * D_F + d];
    }
    __syncthreads();
    // combine stage 2: group 1 dumps, group 0 absorbs
    if (g == 1) {
        float* cb = &cbuf[0][0][0];
        cb[d] = a0;
        #pragma unroll
        for (int j = 0; j < NJ; j++) cb[(1 + j) * D_F + d] = a1[j];
        #pragma unroll
        for (int i = 0; i < 36; i++) cb[(1 + NJ + i) * D_F + d] = a2[i];
    }
    __syncthreads();
    if (g == 0) {
        const float* cb = &cbuf[0][0][0];
        atomicAdd(&g_acc[d], a0 + cb[d]);
        #pragma unroll
        for (int j = 0; j < NJ; j++)
            atomicAdd(&g_acc[(1 + j) * D_F + d], a1[j] + cb[(1 + j) * D_F + d]);
        #pragma unroll
        for (int i = 0; i < 36; i++)
            atomicAdd(&g_acc[(1 + NJ + i) * D_F + d], a2[i] + cb[(1 + NJ + i) * D_F + d]);
    }

    // ---------------- phase 3: last CTA finalizes ---------------------------
    __syncthreads();
    if (tid == 0) {
        __threadfence();                       // my atomics visible before ticket
        unsigned t = atomicAdd(&g_cnt, 1u);
        sflag = (t == NCHUNK - 1) ? 1 : 0;
    }
    __syncthreads();
    if (sflag) {
        __threadfence();
        const float inv = 1.0f / (float)V_NODES;
        for (int idx = tid; idx < NP * D_F; idx += THREADS) {
            int p  = idx >> 7;
            int dd = idx & 127;
            int plane;
            if (p < 1 + NJ) {
                plane = p;
            } else {
                int qq = p - (1 + NJ);
                int j1 = qq >> 3, j2 = qq & 7;
                int lo = j1 < j2 ? j1 : j2;
                int hi = j1 < j2 ? j2 : j1;
                plane = 1 + NJ + lo * NJ - (lo * (lo - 1)) / 2 + (hi - lo);
            }
            out[idx] = __ldcg(&g_acc[plane * D_F + dd]) * inv;
        }
        __syncthreads();                       // all reads done before reset
        for (int idx = tid; idx < NPU * D_F; idx += THREADS) g_acc[idx] = 0.f;
        if (tid == 0) g_cnt = 0u;
    }
}

// ---------------------------------------------------------------------------
extern "C" void kernel_launch(void* const* d_in, const int* in_sizes, int n_in,
                              void* d_out, int out_size) {
    const float* W = (const float*)d_in[0];
    const float* f = (const float*)d_in[1];
    if (n_in >= 2 && in_sizes[0] != V_NODES * V_NODES) {
        W = (const float*)d_in[1];
        f = (const float*)d_in[0];
    }
    k_fused<<<NCHUNK, THREADS>>>(W, f, (float*)d_out);
}

// round 13
// speedup vs baseline: 1.3137x; 1.3137x over previous
#include <cuda_runtime.h>
#include <math.h>

#define V_NODES 2048
#define D_F     128
#define NJ      8
#define NCHUNK  128
#define VC      (V_NODES / NCHUNK)   // 16 nodes per chunk
#define NP      73                   // 1 + J + J^2 (output planes)
#define NPU     45                   // 1 + J + J*(J+1)/2 (unique planes stored)

#define K1_CTAS     512
#define K1_THREADS  512
#define K1_ROWS     4                // rows per CTA (2048/512)

__device__ float g_lam[NJ * V_NODES];             // lam[j][v]
__device__ float g_partial[NCHUNK * NPU * D_F];   // partial[c][pu][d]

// ---------------------------------------------------------------------------
// Kernel 1: deg[v] = row sums of W, then the 8 filter responses at E.
// 512 CTAs x 512 threads: 4 rows/CTA, 4 warps/row, 4 float4/thread front-
// batched. Small regs/smem -> 4 CTAs/SM resident (64 warps) across all 148
// SMs in one wave: ~2x the in-flight loads of the previous version.
// ---------------------------------------------------------------------------
__global__ void __launch_bounds__(K1_THREADS) k_deg_lam(const float* __restrict__ W) {
    const int warp = threadIdx.x >> 5;            // 0..15
    const int lane = threadIdx.x & 31;
    const int rib  = warp >> 2;                   // row within CTA (0..3)
    const int q    = warp & 3;                    // quarter of the row
    const int row  = blockIdx.x * K1_ROWS + rib;

    const float4* Wr = reinterpret_cast<const float4*>(W + (size_t)row * V_NODES);
    float4 x[4];
    #pragma unroll
    for (int i = 0; i < 4; i++)                   // front-batched MLP=4
        x[i] = __ldcs(&Wr[lane + 32 * q + 128 * i]);
    float s = 0.f;
    #pragma unroll
    for (int i = 0; i < 4; i++)
        s += ((x[i].x + x[i].y) + (x[i].z + x[i].w));
    #pragma unroll
    for (int off = 16; off; off >>= 1) s += __shfl_down_sync(0xffffffffu, s, off);

    __shared__ float sw[16];
    if (lane == 0) sw[warp] = s;
    __syncthreads();

    if (threadIdx.x < K1_ROWS) {
        const int r = blockIdx.x * K1_ROWS + threadIdx.x;
        float deg = ((sw[4 * threadIdx.x] + sw[4 * threadIdx.x + 1]) +
                     (sw[4 * threadIdx.x + 2] + sw[4 * threadIdx.x + 3]));
        // Lmat diagonal entry = deg * dhalf^2, dhalf^2 = 1/max(1,deg); E = |.|
        float dh2  = 1.0f / fmaxf(1.0f, deg);
        float E    = fabsf(deg * dh2);
        float logE = logf(E);
        const float A   = 3.0f * 0.69314718055994531f / 6.0f;  // R*ln(2)/(J-R+1)
        const float PI2 = 6.28318530717958648f;
        float ssum = 1.125f;   // (R/2)*sum(d^2) + (R/2)*d0^2
        #pragma unroll
        for (int j = 2; j <= NJ; j++) {
            float xx  = logE - A * (float)(j - 1) / 3.0f;
            float wav = 0.0f;
            if (xx > -A && xx <= 0.0f)
                wav = 0.5f - 0.5f * cosf(PI2 * xx / A);  // d=(0.5,0.5),K=1 closed form
            ssum -= wav * wav;
            g_lam[(j - 1) * V_NODES + r] = wav;
        }
        g_lam[r] = sqrtf(fmaxf(ssum, 0.0f));             // scaling function
    }
}

// ---------------------------------------------------------------------------
// Kernel 2: per v-chunk partial sums; stores ONLY the 45 unique planes:
//   plane 0        : sum_v f[v,d]
//   planes 1..8    : sum_v lam_j[v] * |f[v,d]|
//   planes 9..44   : sum_v lam_j1*lam_j2*|f[v,d]| for j1<=j2 (upper triangle)
// ---------------------------------------------------------------------------
__global__ void __launch_bounds__(128) k_accum(const float* __restrict__ f) {
    const int tid = threadIdx.x;       // d index
    const int c   = blockIdx.x;
    const int v0  = c * VC;

    __shared__ float sl[NJ][VC];
    {
        int j = tid >> 4, vv = tid & 15;   // 8*16 = 128 loads, one per thread
        sl[j][vv] = g_lam[j * V_NODES + v0 + vv];
    }
    __syncthreads();

    float a0 = 0.f, a1[NJ], a2[36];
    #pragma unroll
    for (int i = 0; i < NJ; i++) a1[i] = 0.f;
    #pragma unroll
    for (int i = 0; i < 36; i++) a2[i] = 0.f;

    #pragma unroll
    for (int v = 0; v < VC; v++) {
        float fv = f[(size_t)(v0 + v) * D_F + tid];
        float af = fabsf(fv);
        a0 += fv;
        float w[NJ], p[NJ];
        #pragma unroll
        for (int j = 0; j < NJ; j++) {
            w[j] = sl[j][v];
            p[j] = w[j] * af;
            a1[j] += p[j];
        }
        int idx = 0;
        #pragma unroll
        for (int j1 = 0; j1 < NJ; j1++) {
            #pragma unroll
            for (int j2 = j1; j2 < NJ; j2++) {
                a2[idx] += w[j2] * p[j1];
                idx++;
            }
        }
    }

    float* pp = g_partial + (size_t)c * (NPU * D_F);
    pp[tid] = a0;
    #pragma unroll
    for (int j = 0; j < NJ; j++) pp[(1 + j) * D_F + tid] = a1[j];
    #pragma unroll
    for (int i = 0; i < 36; i++) pp[(1 + NJ + i) * D_F + tid] = a2[i];
}

// ---------------------------------------------------------------------------
// Kernel 3: deterministic fixed-order reduction over the 128 chunks + /V.
// 73 blocks x 512 threads; each output plane maps to its unique stored plane
// (symmetric (j1,j2) pairs read the same plane -> L2 hits).
// ---------------------------------------------------------------------------
__global__ void __launch_bounds__(512) k_reduce(float* __restrict__ out) {
    const int t = threadIdx.x & 127;
    const int q = threadIdx.x >> 7;          // 0..3 (four 32-chunk lanes)
    const int p = blockIdx.x;                // output plane 0..72

    int plane;
    if (p < 1 + NJ) {
        plane = p;
    } else {
        int qq = p - (1 + NJ);
        int j1 = qq >> 3, j2 = qq & 7;
        int lo = j1 < j2 ? j1 : j2;
        int hi = j1 < j2 ? j2 : j1;
        plane = 1 + NJ + lo * NJ - (lo * (lo - 1)) / 2 + (hi - lo);
    }

    const int c0 = q * (NCHUNK / 4);
    float s = 0.f;
    #pragma unroll
    for (int i = 0; i < NCHUNK / 4; i++)
        s += g_partial[(size_t)(c0 + i) * (NPU * D_F) + plane * D_F + t];

    __shared__ float sh[4][D_F];
    sh[q][t] = s;
    __syncthreads();
    if (q == 0) {
        float r = ((sh[0][t] + sh[1][t]) + sh[2][t]) + sh[3][t];
        out[p * D_F + t] = r * (1.0f / (float)V_NODES);
    }
}

// ---------------------------------------------------------------------------
extern "C" void kernel_launch(void* const* d_in, const int* in_sizes, int n_in,
                              void* d_out, int out_size) {
    // metadata order: W [V,V], f [V,d_f]; identify defensively by size.
    const float* W = (const float*)d_in[0];
    const float* f = (const float*)d_in[1];
    if (n_in >= 2 && in_sizes[0] != V_NODES * V_NODES) {
        W = (const float*)d_in[1];
        f = (const float*)d_in[0];
    }
    float* out = (float*)d_out;

    k_deg_lam<<<K1_CTAS, K1_THREADS>>>(W);
    k_accum  <<<NCHUNK, 128>>>(f);
    k_reduce <<<NP, 512>>>(out);
}